// round 10
// baseline (speedup 1.0000x reference)
#include <cuda_runtime.h>
#include <cuda_bf16.h>
#include <cuda_fp16.h>
#include <cstdint>

// ---------------------------------------------------------------------------
// Problem constants
// ---------------------------------------------------------------------------
#define BATCH 128
#define TLEN  4096
#define HID   13
#define G4    52
#define NSEQ  256

// Chunked recurrence: KCH chunks of CH, WARM warmup steps from zero state.
// W=64 validated bit-identical vs exact; W=48 leaves ~e^-33 typical residual.
#define KCH       32
#define KCH_SHIFT 5
#define CH        128
#define WARM      48

// ---------------------------------------------------------------------------
// Scratch (device globals — no allocation allowed)
// ---------------------------------------------------------------------------
// g_pre fp16: per (seq,t) row = 13 k-groups of [(0.5i,0.5f),(g,0.5o)]
__device__ __half g_pre[(size_t)NSEQ * TLEN * G4];       // 109 MB
__device__ __half g_yA[(size_t)NSEQ * TLEN * HID];       // fp16 y scratch
__device__ __half g_yB[(size_t)NSEQ * TLEN * HID];

typedef unsigned long long u64;

// ---------------------------------------------------------------------------
// f32x2 packed helpers
// ---------------------------------------------------------------------------
__device__ __forceinline__ u64 pk2(float x, float y) {
    u64 r; asm("mov.b64 %0, {%1, %2};" : "=l"(r) : "f"(x), "f"(y)); return r;
}
__device__ __forceinline__ float2 upk2(u64 v) {
    float2 r; asm("mov.b64 {%0, %1}, %2;" : "=f"(r.x), "=f"(r.y) : "l"(v)); return r;
}
__device__ __forceinline__ u64 fma2(u64 a, u64 b, u64 c) {
    u64 d; asm("fma.rn.f32x2 %0, %1, %2, %3;" : "=l"(d) : "l"(a), "l"(b), "l"(c)); return d;
}
__device__ __forceinline__ u64 add2(u64 a, u64 b) {
    u64 d; asm("add.rn.f32x2 %0, %1, %2;" : "=l"(d) : "l"(a), "l"(b)); return d;
}

__device__ __forceinline__ float tanha(float x) {
    float r; asm("tanh.approx.f32 %0, %1;" : "=f"(r) : "f"(x)); return r;
}

// cp.async helpers
__device__ __forceinline__ void cp16(unsigned sdst, const void* gsrc) {
    asm volatile("cp.async.cg.shared.global [%0], [%1], 16;"
                 :: "r"(sdst), "l"(gsrc) : "memory");
}
__device__ __forceinline__ void cp8(unsigned sdst, const void* gsrc) {
    asm volatile("cp.async.ca.shared.global [%0], [%1], 8;"
                 :: "r"(sdst), "l"(gsrc) : "memory");
}
__device__ __forceinline__ void cp_commit() {
    asm volatile("cp.async.commit_group;" ::: "memory");
}
__device__ __forceinline__ void cp_wait0() {
    asm volatile("cp.async.wait_group 0;" ::: "memory");
}
__device__ __forceinline__ void cp_wait1() {
    asm volatile("cp.async.wait_group 1;" ::: "memory");
}
__device__ __forceinline__ void cp_wait2() {
    asm volatile("cp.async.wait_group 2;" ::: "memory");
}

// ---------------------------------------------------------------------------
// Pre kernel, layer 0 (D=13, fp32 x input). Block = (seq, 4 tiles of 128).
// ---------------------------------------------------------------------------
__global__ void __launch_bounds__(128)
pre0_kernel(const float* __restrict__ x,
            const float* __restrict__ w_ih,   // [2][52][13]
            const float* __restrict__ b_ih,
            const float* __restrict__ b_hh,
            __half* __restrict__ pre)
{
    __shared__ alignas(16) u64 wp[13 * 26];
    __shared__ u64 bp[26];
    __shared__ alignas(16) float xs[2][128 * 13];
    __shared__ alignas(16) unsigned ot[128 * 26];

    const int tid = threadIdx.x;
    const int seq = blockIdx.x >> 3;
    const int bc  = blockIdx.x & 7;
    const int dir = seq >> 7;
    const int b   = seq & 127;

    const float* W = w_ih + dir * G4 * 13;
    for (int idx = tid; idx < 13 * 26; idx += 128) {
        const int d = idx / 26, m = idx % 26;
        const int k = m % 13, s = m / 13;
        const int j0 = s ? 26 + k : k;
        const float s0 = s ? 1.0f : 0.5f;
        wp[idx] = pk2(s0 * W[j0 * 13 + d], 0.5f * W[(j0 + 13) * 13 + d]);
    }
    if (tid < 26) {
        const int k = tid % 13, s = tid / 13;
        const int j0 = s ? 26 + k : k;
        const float s0 = s ? 1.0f : 0.5f;
        const float* bi = b_ih + dir * G4;
        const float* bh = b_hh + dir * G4;
        bp[tid] = pk2(s0 * (bi[j0] + bh[j0]),
                      0.5f * (bi[j0 + 13] + bh[j0 + 13]));
    }

    const int tile0 = bc * 4;
    const char* xsrc0 = (const char*)(x + ((size_t)b * TLEN + tile0 * 128) * 13);
    const unsigned xs0 = (unsigned)__cvta_generic_to_shared(&xs[0][0]);
    const unsigned xs1 = (unsigned)__cvta_generic_to_shared(&xs[1][0]);
    const unsigned XB  = 128 * 13 * 4;

    for (int i = tid; i < 416; i += 128)
        cp16(xs0 + i * 16, xsrc0 + i * 16);
    cp_commit();

    for (int it = 0; it < 4; it++) {
        if (it < 3) {
            const unsigned dst = ((it + 1) & 1) ? xs1 : xs0;
            const char* src = xsrc0 + (size_t)(it + 1) * XB;
            for (int i = tid; i < 416; i += 128)
                cp16(dst + i * 16, src + i * 16);
            cp_commit();
            cp_wait1();
        } else {
            cp_wait0();
        }
        __syncthreads();

        const float* xc = xs[it & 1];
        u64 acc[26];
#pragma unroll
        for (int m = 0; m < 26; m++) acc[m] = bp[m];
#pragma unroll
        for (int d = 0; d < 13; d++) {
            const float xv = xc[tid * 13 + d];
            const u64 x2 = pk2(xv, xv);
            const ulonglong2* row = (const ulonglong2*)(wp + d * 26);
#pragma unroll
            for (int mm = 0; mm < 13; mm++) {
                const ulonglong2 w2 = row[mm];
                acc[2 * mm]     = fma2(w2.x, x2, acc[2 * mm]);
                acc[2 * mm + 1] = fma2(w2.y, x2, acc[2 * mm + 1]);
            }
        }

#pragma unroll
        for (int k = 0; k < 13; k++) {
            const float2 pif = upk2(acc[k]);
            const float2 pgo = upk2(acc[13 + k]);
            const __half2 hif = __floats2half2_rn(pif.x, pif.y);
            const __half2 hgo = __floats2half2_rn(pgo.x, pgo.y);
            ot[tid * 26 + 2 * k]     = *(const unsigned*)&hif;
            ot[tid * 26 + 2 * k + 1] = *(const unsigned*)&hgo;
        }
        __syncthreads();

        uint4* preb = (uint4*)(pre + ((size_t)seq * TLEN + (tile0 + it) * 128) * G4);
        const uint4* ot4 = (const uint4*)ot;
        for (int j = tid; j < 832; j += 128) preb[j] = ot4[j];
        __syncthreads();
    }
}

// ---------------------------------------------------------------------------
// Pre kernel, layers 1-3 (D=26, reads fp16 y scratch [seq][t][13]).
// ---------------------------------------------------------------------------
__global__ void __launch_bounds__(128)
preR_kernel(const __half* __restrict__ y,     // [NSEQ][TLEN][13] fp16
            const float* __restrict__ w_ih,   // [2][52][26]
            const float* __restrict__ b_ih,
            const float* __restrict__ b_hh,
            __half* __restrict__ pre)
{
    __shared__ alignas(16) u64 wp[26 * 26];
    __shared__ u64 bp[26];
    __shared__ alignas(16) __half fb[2][128 * 13];
    __shared__ alignas(16) __half bb[2][128 * 13];
    __shared__ alignas(16) unsigned ot[128 * 26];

    const int tid = threadIdx.x;
    const int seq = blockIdx.x >> 3;
    const int bc  = blockIdx.x & 7;
    const int dir = seq >> 7;
    const int b   = seq & 127;

    const float* W = w_ih + dir * G4 * 26;
    for (int idx = tid; idx < 26 * 26; idx += 128) {
        const int d = idx / 26, m = idx % 26;
        const int k = m % 13, s = m / 13;
        const int j0 = s ? 26 + k : k;
        const float s0 = s ? 1.0f : 0.5f;
        wp[idx] = pk2(s0 * W[j0 * 26 + d], 0.5f * W[(j0 + 13) * 26 + d]);
    }
    if (tid < 26) {
        const int k = tid % 13, s = tid / 13;
        const int j0 = s ? 26 + k : k;
        const float s0 = s ? 1.0f : 0.5f;
        const float* bi = b_ih + dir * G4;
        const float* bh = b_hh + dir * G4;
        bp[tid] = pk2(s0 * (bi[j0] + bh[j0]),
                      0.5f * (bi[j0 + 13] + bh[j0 + 13]));
    }

    const int tile0 = bc * 4;
    // tile = 128 rows x 13 halves = 3328 B = 208 x 16B
    const char* fsrc0 = (const char*)(y + ((size_t)b * TLEN + tile0 * 128) * 13);
    const char* bsrc0 = (const char*)(y + ((size_t)(BATCH + b) * TLEN + tile0 * 128) * 13);
    const unsigned f0 = (unsigned)__cvta_generic_to_shared(&fb[0][0]);
    const unsigned f1 = (unsigned)__cvta_generic_to_shared(&fb[1][0]);
    const unsigned g0 = (unsigned)__cvta_generic_to_shared(&bb[0][0]);
    const unsigned g1 = (unsigned)__cvta_generic_to_shared(&bb[1][0]);
    const unsigned XB = 128 * 13 * 2;

    for (int i = tid; i < 208; i += 128) {
        cp16(f0 + i * 16, fsrc0 + i * 16);
        cp16(g0 + i * 16, bsrc0 + i * 16);
    }
    cp_commit();

    for (int it = 0; it < 4; it++) {
        if (it < 3) {
            const unsigned fd = ((it + 1) & 1) ? f1 : f0;
            const unsigned gd = ((it + 1) & 1) ? g1 : g0;
            const char* fs = fsrc0 + (size_t)(it + 1) * XB;
            const char* gs = bsrc0 + (size_t)(it + 1) * XB;
            for (int i = tid; i < 208; i += 128) {
                cp16(fd + i * 16, fs + i * 16);
                cp16(gd + i * 16, gs + i * 16);
            }
            cp_commit();
            cp_wait1();
        } else {
            cp_wait0();
        }
        __syncthreads();

        const __half* xf = fb[it & 1];
        const __half* xb = bb[it & 1];
        u64 acc[26];
#pragma unroll
        for (int m = 0; m < 26; m++) acc[m] = bp[m];
#pragma unroll
        for (int d = 0; d < 26; d++) {
            const float xv = (d < 13) ? __half2float(xf[tid * 13 + d])
                                      : __half2float(xb[tid * 13 + (d - 13)]);
            const u64 x2 = pk2(xv, xv);
            const ulonglong2* row = (const ulonglong2*)(wp + d * 26);
#pragma unroll
            for (int mm = 0; mm < 13; mm++) {
                const ulonglong2 w2 = row[mm];
                acc[2 * mm]     = fma2(w2.x, x2, acc[2 * mm]);
                acc[2 * mm + 1] = fma2(w2.y, x2, acc[2 * mm + 1]);
            }
        }

#pragma unroll
        for (int k = 0; k < 13; k++) {
            const float2 pif = upk2(acc[k]);
            const float2 pgo = upk2(acc[13 + k]);
            const __half2 hif = __floats2half2_rn(pif.x, pif.y);
            const __half2 hgo = __floats2half2_rn(pgo.x, pgo.y);
            ot[tid * 26 + 2 * k]     = *(const unsigned*)&hif;
            ot[tid * 26 + 2 * k + 1] = *(const unsigned*)&hgo;
        }
        __syncthreads();

        uint4* preb = (uint4*)(pre + ((size_t)seq * TLEN + (tile0 + it) * 128) * G4);
        const uint4* ot4 = (const uint4*)ot;
        for (int j = tid; j < 832; j += 128) preb[j] = ot4[j];
        __syncthreads();
    }
}

// ---------------------------------------------------------------------------
// Chunked recurrence: KCH=32 (2x warp parallelism), WARM=48. fp16 pre input,
// templated output type (fp16 scratch / fp32 final).
// ---------------------------------------------------------------------------
template<typename OutT>
__global__ void __launch_bounds__(32)
lstm_rec_kernel(const __half* __restrict__ pre,  // [NSEQ][TLEN][52] fp16
                const float* __restrict__ w_hh,  // [2][52][13]
                OutT* __restrict__ yout,
                int ldy, size_t dirOff)
{
    __shared__ alignas(16) uint2 ring[16][32];

    const int lane = threadIdx.x;
    const int b    = blockIdx.x >> KCH_SHIFT;
    const int c    = blockIdx.x & (KCH - 1);
    const int dir  = lane >> 4;
    const int k    = lane & 15;
    const int kc   = (k < 13) ? k : 12;
    const bool act = (k < 13);

    const int Wc   = (c == 0) ? 0 : WARM;
    const int TOT  = Wc + CH;

    const float* W = w_hh + dir * G4 * HID;
    u64 wA[13], wB[13];
#pragma unroll
    for (int kk = 0; kk < 13; kk++) {
        wA[kk] = pk2(0.5f * W[kc * HID + kk], 0.5f * W[(13 + kc) * HID + kk]);
        wB[kk] = pk2(W[(26 + kc) * HID + kk], 0.5f * W[(39 + kc) * HID + kk]);
    }

    const int t0f = c * CH - Wc;
    const int t0b = (KCH - 1 - c) * CH + (CH - 1) + Wc;
    const int tstart = dir ? t0b : t0f;
    const long long ss   = (dir ? -1LL : 1LL) * (long long)(G4 * sizeof(__half));
    const long long ydel = (dir ? -1LL : 1LL) * ldy;

    const int seq = dir * BATCH + b;
    const char* psrc_pf = (const char*)(pre + ((size_t)seq * TLEN + tstart) * G4 + kc * 4);
    OutT* yp = yout + (size_t)b * TLEN * ldy + (size_t)dir * dirOff
                    + (size_t)tstart * ldy + k;

    const unsigned sbase = (unsigned)__cvta_generic_to_shared(&ring[0][lane]);
    const unsigned S8    = (unsigned)(32 * sizeof(uint2));

#pragma unroll
    for (int g = 0; g < 2; g++) {
#pragma unroll
        for (int j = 0; j < 4; j++) {
            cp8(sbase + (g * 4 + j) * S8, psrc_pf);
            psrc_pf += ss;
        }
        cp_commit();
    }

    float h = 0.0f, cv = 0.0f;

    for (int sblk = 0; sblk < TOT; sblk += 16) {
        const bool real = (sblk >= Wc);   // WARM multiple of 16 -> uniform
#pragma unroll
        for (int qq = 0; qq < 4; qq++) {
            const int bs = sblk + qq * 4;
            if (bs + 8 < TOT) {
                const unsigned qs = (((unsigned)(bs >> 2) + 2u) & 3u) * 4u;
#pragma unroll
                for (int j = 0; j < 4; j++)
                    cp8(sbase + (qs + j) * S8, psrc_pf + (long long)j * ss);
            }
            cp_commit();
            psrc_pf += 4 * ss;
            cp_wait2();

#pragma unroll
            for (int j = 0; j < 4; j++) {
                const uint2 rv = ring[qq * 4 + j][lane];
                const float2 pif = __half22float2(*(const __half2*)&rv.x);
                const float2 pgo = __half22float2(*(const __half2*)&rv.y);

                u64 a0 = pk2(pif.x, pif.y), a1 = pk2(pgo.x, pgo.y);
                u64 c0 = 0ull, c1 = 0ull;
#pragma unroll
                for (int kk = 0; kk < 13; kk++) {
                    const float hv = __shfl_sync(0xffffffffu, h, kk, 16);
                    const u64 h2 = pk2(hv, hv);
                    if (kk & 1) { c0 = fma2(wA[kk], h2, c0); c1 = fma2(wB[kk], h2, c1); }
                    else        { a0 = fma2(wA[kk], h2, a0); a1 = fma2(wB[kk], h2, a1); }
                }
                a0 = add2(a0, c0);
                a1 = add2(a1, c1);

                const float2 g01 = upk2(a0);
                const float2 g23 = upk2(a1);
                const float tg = tanha(g23.x);
                const float si = fmaf(0.5f, tanha(g01.x), 0.5f);
                const float sf = fmaf(0.5f, tanha(g01.y), 0.5f);
                const float so = fmaf(0.5f, tanha(g23.y), 0.5f);

                cv = fmaf(sf, cv, si * tg);
                h = so * tanha(cv);

                if (act && real) *yp = (OutT)h;
                yp += ydel;
            }
        }
    }
}

// ---------------------------------------------------------------------------
// Launch
// ---------------------------------------------------------------------------
extern "C" void kernel_launch(void* const* d_in, const int* in_sizes, int n_in,
                              void* d_out, int out_size)
{
    const float* x      = (const float*)d_in[0];
    const float* w_ih0  = (const float*)d_in[1];
    const float* w_hh0  = (const float*)d_in[2];
    const float* b_ih0  = (const float*)d_in[3];
    const float* b_hh0  = (const float*)d_in[4];
    const float* w_ihr  = (const float*)d_in[5];
    const float* w_hhr  = (const float*)d_in[6];
    const float* b_ihr  = (const float*)d_in[7];
    const float* b_hhr  = (const float*)d_in[8];
    float* out = (float*)d_out;

    __half *pre, *yA, *yB;
    cudaGetSymbolAddress((void**)&pre, g_pre);
    cudaGetSymbolAddress((void**)&yA,  g_yA);
    cudaGetSymbolAddress((void**)&yB,  g_yB);

    const int PRE_BLOCKS = NSEQ * 8;              // 2048 (4 tiles each)
    const int REC_BLOCKS = BATCH * KCH;           // 4096
    const size_t Y_DIROFF = (size_t)BATCH * TLEN * HID;

    // Layer 0
    pre0_kernel<<<PRE_BLOCKS, 128>>>(x, w_ih0, b_ih0, b_hh0, pre);
    lstm_rec_kernel<__half><<<REC_BLOCKS, 32>>>(pre, w_hh0, yA, HID, Y_DIROFF);

    // Layers 1-2 -> fp16 scratch; layer 3 -> final fp32 output [B][T][26]
    const __half* ins[3] = {yA, yB, yA};
    for (int l = 0; l < 3; l++) {
        preR_kernel<<<PRE_BLOCKS, 128>>>(ins[l],
                                         w_ihr + (size_t)l * 2 * G4 * 26,
                                         b_ihr + (size_t)l * 2 * G4,
                                         b_hhr + (size_t)l * 2 * G4,
                                         pre);
        if (l < 2) {
            __half* yo = (l == 0) ? yB : yA;
            lstm_rec_kernel<__half><<<REC_BLOCKS, 32>>>(pre,
                                                w_hhr + (size_t)l * 2 * G4 * HID,
                                                yo, HID, Y_DIROFF);
        } else {
            lstm_rec_kernel<float><<<REC_BLOCKS, 32>>>(pre,
                                                w_hhr + (size_t)l * 2 * G4 * HID,
                                                out, 26, (size_t)HID);
        }
    }
}

// round 11
// speedup vs baseline: 1.0260x; 1.0260x over previous
#include <cuda_runtime.h>
#include <cuda_bf16.h>
#include <cuda_fp16.h>
#include <cstdint>

// ---------------------------------------------------------------------------
// Problem constants
// ---------------------------------------------------------------------------
#define BATCH 128
#define TLEN  4096
#define HID   13
#define G4    52
#define NSEQ  256
#define YROW  16        // padded y row (13 real + 3 zero pads)

// Chunked recurrence (validated): KCH chunks of CH, WARM warmup from zero.
#define KCH       32
#define KCH_SHIFT 5
#define CH        128
#define WARM      48

// ---------------------------------------------------------------------------
// Scratch (device globals — no allocation allowed)
// ---------------------------------------------------------------------------
__device__ __half g_pre[(size_t)NSEQ * TLEN * G4];        // 109 MB fp16
__device__ __half g_yA[(size_t)NSEQ * TLEN * YROW];       // padded fp16 y
__device__ __half g_yB[(size_t)NSEQ * TLEN * YROW];

typedef unsigned long long u64;

// ---------------------------------------------------------------------------
// f32x2 packed helpers (rec kernel)
// ---------------------------------------------------------------------------
__device__ __forceinline__ u64 pk2(float x, float y) {
    u64 r; asm("mov.b64 %0, {%1, %2};" : "=l"(r) : "f"(x), "f"(y)); return r;
}
__device__ __forceinline__ float2 upk2(u64 v) {
    float2 r; asm("mov.b64 {%0, %1}, %2;" : "=f"(r.x), "=f"(r.y) : "l"(v)); return r;
}
__device__ __forceinline__ u64 fma2(u64 a, u64 b, u64 c) {
    u64 d; asm("fma.rn.f32x2 %0, %1, %2, %3;" : "=l"(d) : "l"(a), "l"(b), "l"(c)); return d;
}
__device__ __forceinline__ u64 add2(u64 a, u64 b) {
    u64 d; asm("add.rn.f32x2 %0, %1, %2;" : "=l"(d) : "l"(a), "l"(b)); return d;
}
__device__ __forceinline__ float tanha(float x) {
    float r; asm("tanh.approx.f32 %0, %1;" : "=f"(r) : "f"(x)); return r;
}

// cp.async helpers
__device__ __forceinline__ void cp16(unsigned sdst, const void* gsrc) {
    asm volatile("cp.async.cg.shared.global [%0], [%1], 16;"
                 :: "r"(sdst), "l"(gsrc) : "memory");
}
__device__ __forceinline__ void cp8(unsigned sdst, const void* gsrc) {
    asm volatile("cp.async.ca.shared.global [%0], [%1], 8;"
                 :: "r"(sdst), "l"(gsrc) : "memory");
}
__device__ __forceinline__ void cp_commit() {
    asm volatile("cp.async.commit_group;" ::: "memory");
}
__device__ __forceinline__ void cp_wait0() {
    asm volatile("cp.async.wait_group 0;" ::: "memory");
}
__device__ __forceinline__ void cp_wait2() {
    asm volatile("cp.async.wait_group 2;" ::: "memory");
}

// ---------------------------------------------------------------------------
// MMA helpers
// ---------------------------------------------------------------------------
__device__ __forceinline__ void ldmat4(unsigned* r, unsigned addr) {
    asm volatile("ldmatrix.sync.aligned.m8n8.x4.shared.b16 {%0,%1,%2,%3}, [%4];"
                 : "=r"(r[0]), "=r"(r[1]), "=r"(r[2]), "=r"(r[3]) : "r"(addr));
}
__device__ __forceinline__ void mma16816(float& d0, float& d1, float& d2, float& d3,
                                         const unsigned* a, const unsigned* b) {
    asm volatile("mma.sync.aligned.m16n8k16.row.col.f32.f16.f16.f32 "
                 "{%0,%1,%2,%3}, {%4,%5,%6,%7}, {%8,%9}, {%0,%1,%2,%3};"
                 : "+f"(d0), "+f"(d1), "+f"(d2), "+f"(d3)
                 : "r"(a[0]), "r"(a[1]), "r"(a[2]), "r"(a[3]), "r"(b[0]), "r"(b[1]));
}
__device__ __forceinline__ unsigned packh2(float x, float y) {
    const __half2 h = __floats2half2_rn(x, y);
    return *(const unsigned*)&h;
}
// gate-column map: n-th position in the interleaved 52-vector ->
// (weight row, scale). order: 4k..4k+3 = (0.5*i_k, 0.5*f_k, g_k, 0.5*o_k)
__device__ __forceinline__ void gatemap(int n, int& row, float& sc) {
    const int kk = n >> 2, q = n & 3;
    row = (q == 0) ? kk : (q == 1) ? 13 + kk : (q == 2) ? 26 + kk : 39 + kk;
    sc  = (q == 2) ? 1.0f : 0.5f;
}

// ---------------------------------------------------------------------------
// Pre kernel, layer 0 (tensor-core). Block = (seq, 256-timestep tile).
// A: 256x16 fp16 (13 real x dims), B: 16x52 weights, D: pre rows.
// ---------------------------------------------------------------------------
__global__ void __launch_bounds__(128)
pre0_kernel(const float* __restrict__ x,
            const float* __restrict__ w_ih,   // [2][52][13]
            const float* __restrict__ b_ih,
            const float* __restrict__ b_hh,
            __half* __restrict__ pre)
{
    __shared__ alignas(16) __half At[256 * 24];   // stride 24 halves (48B), 12KB

    const int tid  = threadIdx.x;
    const int lane = tid & 31;
    const int warp = tid >> 5;
    const int seq  = blockIdx.x >> 4;
    const int t0   = (blockIdx.x & 15) * 256;
    const int dir  = seq >> 7;
    const int b    = seq & 127;
    const int g    = lane >> 2;
    const int tg   = lane & 3;

    const float* W  = w_ih + dir * G4 * 13;
    const float* bi = b_ih + dir * G4;
    const float* bh = b_hh + dir * G4;

    // B fragments (K=16, 1 kstep) + bias (loaded once)
    unsigned bf[7][2];
    float2 bias[7];
#pragma unroll
    for (int t = 0; t < 7; t++) {
        const int nb = 8 * t + g;               // B col for this lane
        int row; float sc; gatemap(nb < 52 ? nb : 0, row, sc);
        const bool bv = (nb < 52);
#pragma unroll
        for (int r = 0; r < 2; r++) {
            const int k0 = tg * 2 + r * 8;
            const float w0 = (bv && k0     < 13) ? sc * W[row * 13 + k0]     : 0.0f;
            const float w1 = (bv && k0 + 1 < 13) ? sc * W[row * 13 + k0 + 1] : 0.0f;
            bf[t][r] = packh2(w0, w1);
        }
        const int n0 = 8 * t + tg * 2;          // D cols for this lane
        int r0, r1; float s0, s1;
        gatemap(n0 < 52 ? n0 : 0, r0, s0);
        gatemap(n0 + 1 < 52 ? n0 + 1 : 0, r1, s1);
        bias[t].x = (n0     < 52) ? s0 * (bi[r0] + bh[r0]) : 0.0f;
        bias[t].y = (n0 + 1 < 52) ? s1 * (bi[r1] + bh[r1]) : 0.0f;
    }

    // zero A (pad cols), then stage x with cvt
    for (int i = tid; i < 256 * 24 / 8; i += 128)
        ((uint4*)At)[i] = make_uint4(0, 0, 0, 0);
    __syncthreads();
    const float* xsrc = x + ((size_t)b * TLEN + t0) * 13;
    for (int i = tid; i < 256 * 13; i += 128) {
        const int r = i / 13, c = i % 13;
        At[r * 24 + c] = __float2half(xsrc[i]);
    }
    __syncthreads();

    const unsigned sA = (unsigned)__cvta_generic_to_shared(At);
    for (int grp = warp; grp < 16; grp += 4) {
        const int rbase = grp * 16;
        unsigned a[4];
        const unsigned addr = sA + (unsigned)((rbase + (lane & 15)) * 48 + ((lane >> 4) & 1) * 16);
        ldmat4(a, addr);

        const size_t rowoff = (size_t)seq * TLEN + t0 + rbase;
        __half* p0 = pre + (rowoff + g) * G4;
        __half* p1 = pre + (rowoff + g + 8) * G4;
#pragma unroll
        for (int t = 0; t < 7; t++) {
            float d0 = bias[t].x, d1 = bias[t].y, d2 = bias[t].x, d3 = bias[t].y;
            mma16816(d0, d1, d2, d3, a, bf[t]);
            const int n0 = 8 * t + tg * 2;
            if (n0 < 52) {
                *(__half2*)(p0 + n0) = __floats2half2_rn(d0, d1);
                *(__half2*)(p1 + n0) = __floats2half2_rn(d2, d3);
            }
        }
    }
}

// ---------------------------------------------------------------------------
// Pre kernel, layers 1-3 (tensor-core). A: 256x32 fp16 (fwd 13 + pad3 +
// bwd 13 + pad3 from padded y scratch), B: 32x52 weights with zero pad rows.
// ---------------------------------------------------------------------------
__global__ void __launch_bounds__(128)
preR_kernel(const __half* __restrict__ y,     // [2][B][T][16] fp16, pads zero
            const float* __restrict__ w_ih,   // [2][52][26]
            const float* __restrict__ b_ih,
            const float* __restrict__ b_hh,
            __half* __restrict__ pre)
{
    __shared__ alignas(16) __half At[256 * 40];   // stride 40 halves (80B), 20KB

    const int tid  = threadIdx.x;
    const int lane = tid & 31;
    const int warp = tid >> 5;
    const int seq  = blockIdx.x >> 4;
    const int t0   = (blockIdx.x & 15) * 256;
    const int dir  = seq >> 7;
    const int b    = seq & 127;
    const int g    = lane >> 2;
    const int tg   = lane & 3;

    const float* W  = w_ih + dir * G4 * 26;
    const float* bi = b_ih + dir * G4;
    const float* bh = b_hh + dir * G4;

    // B fragments (K=32, 2 ksteps) + bias
    unsigned bf[7][2][2];
    float2 bias[7];
#pragma unroll
    for (int t = 0; t < 7; t++) {
        const int nb = 8 * t + g;
        int row; float sc; gatemap(nb < 52 ? nb : 0, row, sc);
        const bool bv = (nb < 52);
#pragma unroll
        for (int s = 0; s < 2; s++) {
#pragma unroll
            for (int r = 0; r < 2; r++) {
                float w[2];
#pragma unroll
                for (int e = 0; e < 2; e++) {
                    const int k = s * 16 + tg * 2 + r * 8 + e;
                    float v = 0.0f;
                    if (bv) {
                        if (k < 13)                 v = sc * W[row * 26 + k];
                        else if (k >= 16 && k < 29) v = sc * W[row * 26 + k - 3];
                    }
                    w[e] = v;
                }
                bf[t][s][r] = packh2(w[0], w[1]);
            }
        }
        const int n0 = 8 * t + tg * 2;
        int r0, r1; float s0, s1;
        gatemap(n0 < 52 ? n0 : 0, r0, s0);
        gatemap(n0 + 1 < 52 ? n0 + 1 : 0, r1, s1);
        bias[t].x = (n0     < 52) ? s0 * (bi[r0] + bh[r0]) : 0.0f;
        bias[t].y = (n0 + 1 < 52) ? s1 * (bi[r1] + bh[r1]) : 0.0f;
    }

    // stage A via cp.async: fwd halves -> cols 0-15, bwd -> cols 16-31
    const char* yf = (const char*)(y + ((size_t)b * TLEN + t0) * YROW);
    const char* yb = (const char*)(y + ((size_t)(BATCH + b) * TLEN + t0) * YROW);
    const unsigned sA = (unsigned)__cvta_generic_to_shared(At);
    for (int i = tid; i < 512; i += 128) {
        const int r = i >> 1, h16 = i & 1;
        cp16(sA + (unsigned)(r * 80 + h16 * 16),      yf + i * 16);
        cp16(sA + (unsigned)(r * 80 + 32 + h16 * 16), yb + i * 16);
    }
    cp_commit();
    cp_wait0();
    __syncthreads();

    for (int grp = warp; grp < 16; grp += 4) {
        const int rbase = grp * 16;
        unsigned a0[4], a1[4];
        const unsigned addr = sA + (unsigned)((rbase + (lane & 15)) * 80 + ((lane >> 4) & 1) * 16);
        ldmat4(a0, addr);         // k 0-15
        ldmat4(a1, addr + 32);    // k 16-31

        const size_t rowoff = (size_t)seq * TLEN + t0 + rbase;
        __half* p0 = pre + (rowoff + g) * G4;
        __half* p1 = pre + (rowoff + g + 8) * G4;
#pragma unroll
        for (int t = 0; t < 7; t++) {
            float d0 = bias[t].x, d1 = bias[t].y, d2 = bias[t].x, d3 = bias[t].y;
            mma16816(d0, d1, d2, d3, a0, bf[t][0]);
            mma16816(d0, d1, d2, d3, a1, bf[t][1]);
            const int n0 = 8 * t + tg * 2;
            if (n0 < 52) {
                *(__half2*)(p0 + n0) = __floats2half2_rn(d0, d1);
                *(__half2*)(p1 + n0) = __floats2half2_rn(d2, d3);
            }
        }
    }
}

// ---------------------------------------------------------------------------
// Chunked recurrence (KCH=32, WARM=48). fp16 pre input; writes padded fp16
// y scratch (ldy=16, zero pads) or final fp32 out (ldy=26).
// ---------------------------------------------------------------------------
template<typename OutT>
__global__ void __launch_bounds__(32)
lstm_rec_kernel(const __half* __restrict__ pre,  // [NSEQ][TLEN][52] fp16
                const float* __restrict__ w_hh,  // [2][52][13]
                OutT* __restrict__ yout,
                int ldy, size_t dirOff)
{
    __shared__ alignas(16) uint2 ring[16][32];

    const int lane = threadIdx.x;
    const int b    = blockIdx.x >> KCH_SHIFT;
    const int c    = blockIdx.x & (KCH - 1);
    const int dir  = lane >> 4;
    const int k    = lane & 15;
    const int kc   = (k < 13) ? k : 12;
    const bool act = (k < 13);
    const bool padw = (ldy == YROW) && !act;     // zero the y pads

    const int Wc  = (c == 0) ? 0 : WARM;
    const int TOT = Wc + CH;

    const float* W = w_hh + dir * G4 * HID;
    u64 wA[13], wB[13];
#pragma unroll
    for (int kk = 0; kk < 13; kk++) {
        wA[kk] = pk2(0.5f * W[kc * HID + kk], 0.5f * W[(13 + kc) * HID + kk]);
        wB[kk] = pk2(W[(26 + kc) * HID + kk], 0.5f * W[(39 + kc) * HID + kk]);
    }

    const int t0f = c * CH - Wc;
    const int t0b = (KCH - 1 - c) * CH + (CH - 1) + Wc;
    const int tstart = dir ? t0b : t0f;
    const long long ss   = (dir ? -1LL : 1LL) * (long long)(G4 * sizeof(__half));
    const long long ydel = (dir ? -1LL : 1LL) * ldy;

    const int seq = dir * BATCH + b;
    const char* psrc_pf = (const char*)(pre + ((size_t)seq * TLEN + tstart) * G4 + kc * 4);
    OutT* yp = yout + (size_t)b * TLEN * ldy + (size_t)dir * dirOff
                    + (size_t)tstart * ldy + k;

    const unsigned sbase = (unsigned)__cvta_generic_to_shared(&ring[0][lane]);
    const unsigned S8    = (unsigned)(32 * sizeof(uint2));

#pragma unroll
    for (int g = 0; g < 2; g++) {
#pragma unroll
        for (int j = 0; j < 4; j++) {
            cp8(sbase + (g * 4 + j) * S8, psrc_pf);
            psrc_pf += ss;
        }
        cp_commit();
    }

    float h = 0.0f, cv = 0.0f;

    for (int sblk = 0; sblk < TOT; sblk += 16) {
        const bool real = (sblk >= Wc);
#pragma unroll
        for (int qq = 0; qq < 4; qq++) {
            const int bs = sblk + qq * 4;
            if (bs + 8 < TOT) {
                const unsigned qs = (((unsigned)(bs >> 2) + 2u) & 3u) * 4u;
#pragma unroll
                for (int j = 0; j < 4; j++)
                    cp8(sbase + (qs + j) * S8, psrc_pf + (long long)j * ss);
            }
            cp_commit();
            psrc_pf += 4 * ss;
            cp_wait2();

#pragma unroll
            for (int j = 0; j < 4; j++) {
                const uint2 rv = ring[qq * 4 + j][lane];
                const float2 pif = __half22float2(*(const __half2*)&rv.x);
                const float2 pgo = __half22float2(*(const __half2*)&rv.y);

                u64 a0 = pk2(pif.x, pif.y), a1 = pk2(pgo.x, pgo.y);
                u64 c0 = 0ull, c1 = 0ull;
#pragma unroll
                for (int kk = 0; kk < 13; kk++) {
                    const float hv = __shfl_sync(0xffffffffu, h, kk, 16);
                    const u64 h2 = pk2(hv, hv);
                    if (kk & 1) { c0 = fma2(wA[kk], h2, c0); c1 = fma2(wB[kk], h2, c1); }
                    else        { a0 = fma2(wA[kk], h2, a0); a1 = fma2(wB[kk], h2, a1); }
                }
                a0 = add2(a0, c0);
                a1 = add2(a1, c1);

                const float2 g01 = upk2(a0);
                const float2 g23 = upk2(a1);
                const float tg = tanha(g23.x);
                const float si = fmaf(0.5f, tanha(g01.x), 0.5f);
                const float sf = fmaf(0.5f, tanha(g01.y), 0.5f);
                const float so = fmaf(0.5f, tanha(g23.y), 0.5f);

                cv = fmaf(sf, cv, si * tg);
                h = so * tanha(cv);

                if (real) {
                    if (act)       *yp = (OutT)h;
                    else if (padw) *yp = (OutT)0.0f;
                }
                yp += ydel;
            }
        }
    }
}

// ---------------------------------------------------------------------------
// Launch
// ---------------------------------------------------------------------------
extern "C" void kernel_launch(void* const* d_in, const int* in_sizes, int n_in,
                              void* d_out, int out_size)
{
    const float* x      = (const float*)d_in[0];
    const float* w_ih0  = (const float*)d_in[1];
    const float* w_hh0  = (const float*)d_in[2];
    const float* b_ih0  = (const float*)d_in[3];
    const float* b_hh0  = (const float*)d_in[4];
    const float* w_ihr  = (const float*)d_in[5];
    const float* w_hhr  = (const float*)d_in[6];
    const float* b_ihr  = (const float*)d_in[7];
    const float* b_hhr  = (const float*)d_in[8];
    float* out = (float*)d_out;

    __half *pre, *yA, *yB;
    cudaGetSymbolAddress((void**)&pre, g_pre);
    cudaGetSymbolAddress((void**)&yA,  g_yA);
    cudaGetSymbolAddress((void**)&yB,  g_yB);

    const int PRE_BLOCKS = NSEQ * 16;             // 4096 (256-t tiles)
    const int REC_BLOCKS = BATCH * KCH;           // 4096
    const size_t Y_DIROFF = (size_t)BATCH * TLEN * YROW;

    // Layer 0
    pre0_kernel<<<PRE_BLOCKS, 128>>>(x, w_ih0, b_ih0, b_hh0, pre);
    lstm_rec_kernel<__half><<<REC_BLOCKS, 32>>>(pre, w_hh0, yA, YROW, Y_DIROFF);

    // Layers 1-2 -> padded fp16 scratch; layer 3 -> final fp32 out [B][T][26]
    const __half* ins[3] = {yA, yB, yA};
    for (int l = 0; l < 3; l++) {
        preR_kernel<<<PRE_BLOCKS, 128>>>(ins[l],
                                         w_ihr + (size_t)l * 2 * G4 * 26,
                                         b_ihr + (size_t)l * 2 * G4,
                                         b_hhr + (size_t)l * 2 * G4,
                                         pre);
        if (l < 2) {
            __half* yo = (l == 0) ? yB : yA;
            lstm_rec_kernel<__half><<<REC_BLOCKS, 32>>>(pre,
                                                w_hhr + (size_t)l * 2 * G4 * HID,
                                                yo, YROW, Y_DIROFF);
        } else {
            lstm_rec_kernel<float><<<REC_BLOCKS, 32>>>(pre,
                                                w_hhr + (size_t)l * 2 * G4 * HID,
                                                out, 26, (size_t)HID);
        }
    }
}

// round 12
// speedup vs baseline: 1.1826x; 1.1527x over previous
#include <cuda_runtime.h>
#include <cuda_bf16.h>
#include <cuda_fp16.h>
#include <cstdint>

// ---------------------------------------------------------------------------
// Problem constants
// ---------------------------------------------------------------------------
#define BATCH 128
#define TLEN  4096
#define HID   13
#define G4    52
#define NSEQ  256
#define YROW  16        // padded y row (13 real + 3 pads; pads stay zero from
                        // static zero-initialization — never written)

// Chunked recurrence (validated): KCH chunks of CH, WARM warmup from zero.
#define KCH       32
#define KCH_SHIFT 5
#define CH        128
#define WARM      48

// ---------------------------------------------------------------------------
// Scratch (device globals — no allocation allowed; zero-initialized at load)
// ---------------------------------------------------------------------------
__device__ __half g_pre[(size_t)NSEQ * TLEN * G4];        // 109 MB fp16
__device__ __half g_yA[(size_t)NSEQ * TLEN * YROW];       // padded fp16 y
__device__ __half g_yB[(size_t)NSEQ * TLEN * YROW];

typedef unsigned long long u64;

// ---------------------------------------------------------------------------
// f32x2 packed helpers (rec kernel)
// ---------------------------------------------------------------------------
__device__ __forceinline__ u64 pk2(float x, float y) {
    u64 r; asm("mov.b64 %0, {%1, %2};" : "=l"(r) : "f"(x), "f"(y)); return r;
}
__device__ __forceinline__ float2 upk2(u64 v) {
    float2 r; asm("mov.b64 {%0, %1}, %2;" : "=f"(r.x), "=f"(r.y) : "l"(v)); return r;
}
__device__ __forceinline__ u64 fma2(u64 a, u64 b, u64 c) {
    u64 d; asm("fma.rn.f32x2 %0, %1, %2, %3;" : "=l"(d) : "l"(a), "l"(b), "l"(c)); return d;
}
__device__ __forceinline__ u64 add2(u64 a, u64 b) {
    u64 d; asm("add.rn.f32x2 %0, %1, %2;" : "=l"(d) : "l"(a), "l"(b)); return d;
}
__device__ __forceinline__ float tanha(float x) {
    float r; asm("tanh.approx.f32 %0, %1;" : "=f"(r) : "f"(x)); return r;
}

// cp.async helpers
__device__ __forceinline__ void cp16(unsigned sdst, const void* gsrc) {
    asm volatile("cp.async.cg.shared.global [%0], [%1], 16;"
                 :: "r"(sdst), "l"(gsrc) : "memory");
}
__device__ __forceinline__ void cp8(unsigned sdst, const void* gsrc) {
    asm volatile("cp.async.ca.shared.global [%0], [%1], 8;"
                 :: "r"(sdst), "l"(gsrc) : "memory");
}
__device__ __forceinline__ void cp_commit() {
    asm volatile("cp.async.commit_group;" ::: "memory");
}
__device__ __forceinline__ void cp_wait0() {
    asm volatile("cp.async.wait_group 0;" ::: "memory");
}
__device__ __forceinline__ void cp_wait2() {
    asm volatile("cp.async.wait_group 2;" ::: "memory");
}

// ---------------------------------------------------------------------------
// MMA helpers
// ---------------------------------------------------------------------------
__device__ __forceinline__ void ldmat4(unsigned* r, unsigned addr) {
    asm volatile("ldmatrix.sync.aligned.m8n8.x4.shared.b16 {%0,%1,%2,%3}, [%4];"
                 : "=r"(r[0]), "=r"(r[1]), "=r"(r[2]), "=r"(r[3]) : "r"(addr));
}
__device__ __forceinline__ void mma16816(float& d0, float& d1, float& d2, float& d3,
                                         const unsigned* a, const unsigned* b) {
    asm volatile("mma.sync.aligned.m16n8k16.row.col.f32.f16.f16.f32 "
                 "{%0,%1,%2,%3}, {%4,%5,%6,%7}, {%8,%9}, {%0,%1,%2,%3};"
                 : "+f"(d0), "+f"(d1), "+f"(d2), "+f"(d3)
                 : "r"(a[0]), "r"(a[1]), "r"(a[2]), "r"(a[3]), "r"(b[0]), "r"(b[1]));
}
__device__ __forceinline__ unsigned packh2(float x, float y) {
    const __half2 h = __floats2half2_rn(x, y);
    return *(const unsigned*)&h;
}
// gate-column map: n-th position in interleaved 52-vector -> (row, scale)
__device__ __forceinline__ void gatemap(int n, int& row, float& sc) {
    const int kk = n >> 2, q = n & 3;
    row = (q == 0) ? kk : (q == 1) ? 13 + kk : (q == 2) ? 26 + kk : 39 + kk;
    sc  = (q == 2) ? 1.0f : 0.5f;
}

// ---------------------------------------------------------------------------
// Pre kernel, layer 0 (tensor-core). Block = (seq, 256-timestep tile).
// ---------------------------------------------------------------------------
__global__ void __launch_bounds__(128)
pre0_kernel(const float* __restrict__ x,
            const float* __restrict__ w_ih,   // [2][52][13]
            const float* __restrict__ b_ih,
            const float* __restrict__ b_hh,
            __half* __restrict__ pre)
{
    __shared__ alignas(16) __half At[256 * 24];

    const int tid  = threadIdx.x;
    const int lane = tid & 31;
    const int warp = tid >> 5;
    const int seq  = blockIdx.x >> 4;
    const int t0   = (blockIdx.x & 15) * 256;
    const int dir  = seq >> 7;
    const int b    = seq & 127;
    const int g    = lane >> 2;
    const int tg   = lane & 3;

    const float* W  = w_ih + dir * G4 * 13;
    const float* bi = b_ih + dir * G4;
    const float* bh = b_hh + dir * G4;

    unsigned bf[7][2];
    float2 bias[7];
#pragma unroll
    for (int t = 0; t < 7; t++) {
        const int nb = 8 * t + g;
        int row; float sc; gatemap(nb < 52 ? nb : 0, row, sc);
        const bool bv = (nb < 52);
#pragma unroll
        for (int r = 0; r < 2; r++) {
            const int k0 = tg * 2 + r * 8;
            const float w0 = (bv && k0     < 13) ? sc * W[row * 13 + k0]     : 0.0f;
            const float w1 = (bv && k0 + 1 < 13) ? sc * W[row * 13 + k0 + 1] : 0.0f;
            bf[t][r] = packh2(w0, w1);
        }
        const int n0 = 8 * t + tg * 2;
        int r0, r1; float s0, s1;
        gatemap(n0 < 52 ? n0 : 0, r0, s0);
        gatemap(n0 + 1 < 52 ? n0 + 1 : 0, r1, s1);
        bias[t].x = (n0     < 52) ? s0 * (bi[r0] + bh[r0]) : 0.0f;
        bias[t].y = (n0 + 1 < 52) ? s1 * (bi[r1] + bh[r1]) : 0.0f;
    }

    for (int i = tid; i < 256 * 24 / 8; i += 128)
        ((uint4*)At)[i] = make_uint4(0, 0, 0, 0);
    __syncthreads();
    const float* xsrc = x + ((size_t)b * TLEN + t0) * 13;
    for (int i = tid; i < 256 * 13; i += 128) {
        const int r = i / 13, c = i % 13;
        At[r * 24 + c] = __float2half(xsrc[i]);
    }
    __syncthreads();

    const unsigned sA = (unsigned)__cvta_generic_to_shared(At);
    for (int grp = warp; grp < 16; grp += 4) {
        const int rbase = grp * 16;
        unsigned a[4];
        const unsigned addr = sA + (unsigned)((rbase + (lane & 15)) * 48 + ((lane >> 4) & 1) * 16);
        ldmat4(a, addr);

        const size_t rowoff = (size_t)seq * TLEN + t0 + rbase;
        __half* p0 = pre + (rowoff + g) * G4;
        __half* p1 = pre + (rowoff + g + 8) * G4;
#pragma unroll
        for (int t = 0; t < 7; t++) {
            float d0 = bias[t].x, d1 = bias[t].y, d2 = bias[t].x, d3 = bias[t].y;
            mma16816(d0, d1, d2, d3, a, bf[t]);
            const int n0 = 8 * t + tg * 2;
            if (n0 < 52) {
                *(__half2*)(p0 + n0) = __floats2half2_rn(d0, d1);
                *(__half2*)(p1 + n0) = __floats2half2_rn(d2, d3);
            }
        }
    }
}

// ---------------------------------------------------------------------------
// Pre kernel, layers 1-3 (tensor-core). A: 256x32 (fwd 13+pad3, bwd 13+pad3).
// ---------------------------------------------------------------------------
__global__ void __launch_bounds__(128)
preR_kernel(const __half* __restrict__ y,     // [2][B][T][16] fp16, pads zero
            const float* __restrict__ w_ih,   // [2][52][26]
            const float* __restrict__ b_ih,
            const float* __restrict__ b_hh,
            __half* __restrict__ pre)
{
    __shared__ alignas(16) __half At[256 * 40];

    const int tid  = threadIdx.x;
    const int lane = tid & 31;
    const int warp = tid >> 5;
    const int seq  = blockIdx.x >> 4;
    const int t0   = (blockIdx.x & 15) * 256;
    const int dir  = seq >> 7;
    const int b    = seq & 127;
    const int g    = lane >> 2;
    const int tg   = lane & 3;

    const float* W  = w_ih + dir * G4 * 26;
    const float* bi = b_ih + dir * G4;
    const float* bh = b_hh + dir * G4;

    unsigned bf[7][2][2];
    float2 bias[7];
#pragma unroll
    for (int t = 0; t < 7; t++) {
        const int nb = 8 * t + g;
        int row; float sc; gatemap(nb < 52 ? nb : 0, row, sc);
        const bool bv = (nb < 52);
#pragma unroll
        for (int s = 0; s < 2; s++) {
#pragma unroll
            for (int r = 0; r < 2; r++) {
                float w[2];
#pragma unroll
                for (int e = 0; e < 2; e++) {
                    const int k = s * 16 + tg * 2 + r * 8 + e;
                    float v = 0.0f;
                    if (bv) {
                        if (k < 13)                 v = sc * W[row * 26 + k];
                        else if (k >= 16 && k < 29) v = sc * W[row * 26 + k - 3];
                    }
                    w[e] = v;
                }
                bf[t][s][r] = packh2(w[0], w[1]);
            }
        }
        const int n0 = 8 * t + tg * 2;
        int r0, r1; float s0, s1;
        gatemap(n0 < 52 ? n0 : 0, r0, s0);
        gatemap(n0 + 1 < 52 ? n0 + 1 : 0, r1, s1);
        bias[t].x = (n0     < 52) ? s0 * (bi[r0] + bh[r0]) : 0.0f;
        bias[t].y = (n0 + 1 < 52) ? s1 * (bi[r1] + bh[r1]) : 0.0f;
    }

    const char* yf = (const char*)(y + ((size_t)b * TLEN + t0) * YROW);
    const char* yb = (const char*)(y + ((size_t)(BATCH + b) * TLEN + t0) * YROW);
    const unsigned sA = (unsigned)__cvta_generic_to_shared(At);
    for (int i = tid; i < 512; i += 128) {
        const int r = i >> 1, h16 = i & 1;
        cp16(sA + (unsigned)(r * 80 + h16 * 16),      yf + i * 16);
        cp16(sA + (unsigned)(r * 80 + 32 + h16 * 16), yb + i * 16);
    }
    cp_commit();
    cp_wait0();
    __syncthreads();

    for (int grp = warp; grp < 16; grp += 4) {
        const int rbase = grp * 16;
        unsigned a0[4], a1[4];
        const unsigned addr = sA + (unsigned)((rbase + (lane & 15)) * 80 + ((lane >> 4) & 1) * 16);
        ldmat4(a0, addr);
        ldmat4(a1, addr + 32);

        const size_t rowoff = (size_t)seq * TLEN + t0 + rbase;
        __half* p0 = pre + (rowoff + g) * G4;
        __half* p1 = pre + (rowoff + g + 8) * G4;
#pragma unroll
        for (int t = 0; t < 7; t++) {
            float d0 = bias[t].x, d1 = bias[t].y, d2 = bias[t].x, d3 = bias[t].y;
            mma16816(d0, d1, d2, d3, a0, bf[t][0]);
            mma16816(d0, d1, d2, d3, a1, bf[t][1]);
            const int n0 = 8 * t + tg * 2;
            if (n0 < 52) {
                *(__half2*)(p0 + n0) = __floats2half2_rn(d0, d1);
                *(__half2*)(p1 + n0) = __floats2half2_rn(d2, d3);
            }
        }
    }
}

// ---------------------------------------------------------------------------
// Chunked recurrence (KCH=32, WARM=48). Compile-time output stride LDY;
// single predicated store (no pad writes — pads are statically zero).
// ---------------------------------------------------------------------------
template<typename OutT, int LDY>
__global__ void __launch_bounds__(32)
lstm_rec_kernel(const __half* __restrict__ pre,  // [NSEQ][TLEN][52] fp16
                const float* __restrict__ w_hh,  // [2][52][13]
                OutT* __restrict__ yout,
                size_t dirOff)
{
    __shared__ alignas(16) uint2 ring[16][32];

    const int lane = threadIdx.x;
    const int b    = blockIdx.x >> KCH_SHIFT;
    const int c    = blockIdx.x & (KCH - 1);
    const int dir  = lane >> 4;
    const int k    = lane & 15;
    const int kc   = (k < 13) ? k : 12;
    const bool act = (k < 13);

    const int Wc  = (c == 0) ? 0 : WARM;
    const int TOT = Wc + CH;

    const float* W = w_hh + dir * G4 * HID;
    u64 wA[13], wB[13];
#pragma unroll
    for (int kk = 0; kk < 13; kk++) {
        wA[kk] = pk2(0.5f * W[kc * HID + kk], 0.5f * W[(13 + kc) * HID + kk]);
        wB[kk] = pk2(W[(26 + kc) * HID + kk], 0.5f * W[(39 + kc) * HID + kk]);
    }

    const int t0f = c * CH - Wc;
    const int t0b = (KCH - 1 - c) * CH + (CH - 1) + Wc;
    const int tstart = dir ? t0b : t0f;
    const long long ss   = (dir ? -1LL : 1LL) * (long long)(G4 * sizeof(__half));
    const long long ydel = (dir ? -1LL : 1LL) * LDY;

    const int seq = dir * BATCH + b;
    const char* psrc_pf = (const char*)(pre + ((size_t)seq * TLEN + tstart) * G4 + kc * 4);
    OutT* yp = yout + (size_t)b * TLEN * LDY + (size_t)dir * dirOff
                    + (size_t)tstart * LDY + k;

    const unsigned sbase = (unsigned)__cvta_generic_to_shared(&ring[0][lane]);
    const unsigned S8    = (unsigned)(32 * sizeof(uint2));

#pragma unroll
    for (int g = 0; g < 2; g++) {
#pragma unroll
        for (int j = 0; j < 4; j++) {
            cp8(sbase + (g * 4 + j) * S8, psrc_pf);
            psrc_pf += ss;
        }
        cp_commit();
    }

    float h = 0.0f, cv = 0.0f;

    for (int sblk = 0; sblk < TOT; sblk += 16) {
        const bool real = (sblk >= Wc);
#pragma unroll
        for (int qq = 0; qq < 4; qq++) {
            const int bs = sblk + qq * 4;
            if (bs + 8 < TOT) {
                const unsigned qs = (((unsigned)(bs >> 2) + 2u) & 3u) * 4u;
#pragma unroll
                for (int j = 0; j < 4; j++)
                    cp8(sbase + (qs + j) * S8, psrc_pf + (long long)j * ss);
            }
            cp_commit();
            psrc_pf += 4 * ss;
            cp_wait2();

#pragma unroll
            for (int j = 0; j < 4; j++) {
                const uint2 rv = ring[qq * 4 + j][lane];
                const float2 pif = __half22float2(*(const __half2*)&rv.x);
                const float2 pgo = __half22float2(*(const __half2*)&rv.y);

                u64 a0 = pk2(pif.x, pif.y), a1 = pk2(pgo.x, pgo.y);
                u64 c0 = 0ull, c1 = 0ull;
#pragma unroll
                for (int kk = 0; kk < 13; kk++) {
                    const float hv = __shfl_sync(0xffffffffu, h, kk, 16);
                    const u64 h2 = pk2(hv, hv);
                    if (kk & 1) { c0 = fma2(wA[kk], h2, c0); c1 = fma2(wB[kk], h2, c1); }
                    else        { a0 = fma2(wA[kk], h2, a0); a1 = fma2(wB[kk], h2, a1); }
                }
                a0 = add2(a0, c0);
                a1 = add2(a1, c1);

                const float2 g01 = upk2(a0);
                const float2 g23 = upk2(a1);
                const float tg = tanha(g23.x);
                const float si = fmaf(0.5f, tanha(g01.x), 0.5f);
                const float sf = fmaf(0.5f, tanha(g01.y), 0.5f);
                const float so = fmaf(0.5f, tanha(g23.y), 0.5f);

                cv = fmaf(sf, cv, si * tg);
                h = so * tanha(cv);

                if (act && real) *yp = (OutT)h;
                yp += ydel;
            }
        }
    }
}

// ---------------------------------------------------------------------------
// Launch
// ---------------------------------------------------------------------------
extern "C" void kernel_launch(void* const* d_in, const int* in_sizes, int n_in,
                              void* d_out, int out_size)
{
    const float* x      = (const float*)d_in[0];
    const float* w_ih0  = (const float*)d_in[1];
    const float* w_hh0  = (const float*)d_in[2];
    const float* b_ih0  = (const float*)d_in[3];
    const float* b_hh0  = (const float*)d_in[4];
    const float* w_ihr  = (const float*)d_in[5];
    const float* w_hhr  = (const float*)d_in[6];
    const float* b_ihr  = (const float*)d_in[7];
    const float* b_hhr  = (const float*)d_in[8];
    float* out = (float*)d_out;

    __half *pre, *yA, *yB;
    cudaGetSymbolAddress((void**)&pre, g_pre);
    cudaGetSymbolAddress((void**)&yA,  g_yA);
    cudaGetSymbolAddress((void**)&yB,  g_yB);

    const int PRE_BLOCKS = NSEQ * 16;             // 4096 (256-t tiles)
    const int REC_BLOCKS = BATCH * KCH;           // 4096
    const size_t Y_DIROFF = (size_t)BATCH * TLEN * YROW;

    // Layer 0
    pre0_kernel<<<PRE_BLOCKS, 128>>>(x, w_ih0, b_ih0, b_hh0, pre);
    lstm_rec_kernel<__half, YROW><<<REC_BLOCKS, 32>>>(pre, w_hh0, yA, Y_DIROFF);

    // Layers 1-2 -> padded fp16 scratch; layer 3 -> final fp32 out [B][T][26]
    const __half* ins[3] = {yA, yB, yA};
    for (int l = 0; l < 3; l++) {
        preR_kernel<<<PRE_BLOCKS, 128>>>(ins[l],
                                         w_ihr + (size_t)l * 2 * G4 * 26,
                                         b_ihr + (size_t)l * 2 * G4,
                                         b_hhr + (size_t)l * 2 * G4,
                                         pre);
        if (l < 2) {
            __half* yo = (l == 0) ? yB : yA;
            lstm_rec_kernel<__half, YROW><<<REC_BLOCKS, 32>>>(pre,
                                                w_hhr + (size_t)l * 2 * G4 * HID,
                                                yo, Y_DIROFF);
        } else {
            lstm_rec_kernel<float, 26><<<REC_BLOCKS, 32>>>(pre,
                                                w_hhr + (size_t)l * 2 * G4 * HID,
                                                out, (size_t)HID);
        }
    }
}

// round 13
// speedup vs baseline: 1.4760x; 1.2481x over previous
#include <cuda_runtime.h>
#include <cuda_bf16.h>
#include <cuda_fp16.h>
#include <cstdint>

// ---------------------------------------------------------------------------
// Problem constants
// ---------------------------------------------------------------------------
#define BATCH 128
#define TLEN  4096
#define HID   13
#define G4    52
#define NSEQ  256
#define YROW  16        // padded y row (13 real + 3 pads; pads statically zero)

// Chunked recurrence: KCH chunks of CH, WARM warmup from zero state.
#define KCH       16
#define KCH_SHIFT 4
#define CH        256
#define WARM      48

// ---------------------------------------------------------------------------
// Scratch (device globals — no allocation allowed; zero-initialized at load)
// ---------------------------------------------------------------------------
__device__ __half g_pre[(size_t)NSEQ * TLEN * G4];        // 109 MB fp16
__device__ __half g_yA[(size_t)NSEQ * TLEN * YROW];       // padded fp16 y
__device__ __half g_yB[(size_t)NSEQ * TLEN * YROW];

typedef unsigned long long u64;

// ---------------------------------------------------------------------------
// f32x2 packed helpers (rec kernel)
// ---------------------------------------------------------------------------
__device__ __forceinline__ u64 pk2(float x, float y) {
    u64 r; asm("mov.b64 %0, {%1, %2};" : "=l"(r) : "f"(x), "f"(y)); return r;
}
__device__ __forceinline__ float2 upk2(u64 v) {
    float2 r; asm("mov.b64 {%0, %1}, %2;" : "=f"(r.x), "=f"(r.y) : "l"(v)); return r;
}
__device__ __forceinline__ u64 fma2(u64 a, u64 b, u64 c) {
    u64 d; asm("fma.rn.f32x2 %0, %1, %2, %3;" : "=l"(d) : "l"(a), "l"(b), "l"(c)); return d;
}
__device__ __forceinline__ u64 add2(u64 a, u64 b) {
    u64 d; asm("add.rn.f32x2 %0, %1, %2;" : "=l"(d) : "l"(a), "l"(b)); return d;
}
__device__ __forceinline__ float tanha(float x) {
    float r; asm("tanh.approx.f32 %0, %1;" : "=f"(r) : "f"(x)); return r;
}

// cp.async helpers
__device__ __forceinline__ void cp16(unsigned sdst, const void* gsrc) {
    asm volatile("cp.async.cg.shared.global [%0], [%1], 16;"
                 :: "r"(sdst), "l"(gsrc) : "memory");
}
__device__ __forceinline__ void cp8(unsigned sdst, const void* gsrc) {
    asm volatile("cp.async.ca.shared.global [%0], [%1], 8;"
                 :: "r"(sdst), "l"(gsrc) : "memory");
}
__device__ __forceinline__ void cp_commit() {
    asm volatile("cp.async.commit_group;" ::: "memory");
}
__device__ __forceinline__ void cp_wait0() {
    asm volatile("cp.async.wait_group 0;" ::: "memory");
}
__device__ __forceinline__ void cp_wait2() {
    asm volatile("cp.async.wait_group 2;" ::: "memory");
}

// ---------------------------------------------------------------------------
// MMA helpers
// ---------------------------------------------------------------------------
__device__ __forceinline__ void ldmat4(unsigned* r, unsigned addr) {
    asm volatile("ldmatrix.sync.aligned.m8n8.x4.shared.b16 {%0,%1,%2,%3}, [%4];"
                 : "=r"(r[0]), "=r"(r[1]), "=r"(r[2]), "=r"(r[3]) : "r"(addr));
}
__device__ __forceinline__ void mma16816(float& d0, float& d1, float& d2, float& d3,
                                         const unsigned* a, const unsigned* b) {
    asm volatile("mma.sync.aligned.m16n8k16.row.col.f32.f16.f16.f32 "
                 "{%0,%1,%2,%3}, {%4,%5,%6,%7}, {%8,%9}, {%0,%1,%2,%3};"
                 : "+f"(d0), "+f"(d1), "+f"(d2), "+f"(d3)
                 : "r"(a[0]), "r"(a[1]), "r"(a[2]), "r"(a[3]), "r"(b[0]), "r"(b[1]));
}
__device__ __forceinline__ unsigned packh2(float x, float y) {
    const __half2 h = __floats2half2_rn(x, y);
    return *(const unsigned*)&h;
}
// gate-column map: n-th position in interleaved 52-vector -> (row, scale)
__device__ __forceinline__ void gatemap(int n, int& row, float& sc) {
    const int kk = n >> 2, q = n & 3;
    row = (q == 0) ? kk : (q == 1) ? 13 + kk : (q == 2) ? 26 + kk : 39 + kk;
    sc  = (q == 2) ? 1.0f : 0.5f;
}

// ---------------------------------------------------------------------------
// Pre kernel, layer 0 (tensor-core, BOTH dirs per block). Block = (batch b,
// 256-t tile). Warps 0-1: dir 0; warps 2-3: dir 1. A staged once.
// Output staged per-warp in smem, stored as coalesced uint4 runs.
// ---------------------------------------------------------------------------
__global__ void __launch_bounds__(128)
pre0_kernel(const float* __restrict__ x,
            const float* __restrict__ w_ih,   // [2][52][13]
            const float* __restrict__ b_ih,
            const float* __restrict__ b_hh,
            __half* __restrict__ pre)
{
    __shared__ alignas(16) __half At[256 * 24];       // 12 KB
    __shared__ alignas(16) __half Ot[4][16 * G4];     // 4 x 1664 B

    const int tid  = threadIdx.x;
    const int lane = tid & 31;
    const int warp = tid >> 5;
    const int b    = blockIdx.x >> 4;
    const int t0   = (blockIdx.x & 15) * 256;
    const int dir  = warp >> 1;
    const int g    = lane >> 2;
    const int tg   = lane & 3;

    const float* W  = w_ih + dir * G4 * 13;
    const float* bi = b_ih + dir * G4;
    const float* bh = b_hh + dir * G4;

    unsigned bf[7][2];
    float2 bias[7];
#pragma unroll
    for (int t = 0; t < 7; t++) {
        const int nb = 8 * t + g;
        int row; float sc; gatemap(nb < 52 ? nb : 0, row, sc);
        const bool bv = (nb < 52);
#pragma unroll
        for (int r = 0; r < 2; r++) {
            const int k0 = tg * 2 + r * 8;
            const float w0 = (bv && k0     < 13) ? sc * W[row * 13 + k0]     : 0.0f;
            const float w1 = (bv && k0 + 1 < 13) ? sc * W[row * 13 + k0 + 1] : 0.0f;
            bf[t][r] = packh2(w0, w1);
        }
        const int n0 = 8 * t + tg * 2;
        int r0, r1; float s0, s1;
        gatemap(n0 < 52 ? n0 : 0, r0, s0);
        gatemap(n0 + 1 < 52 ? n0 + 1 : 0, r1, s1);
        bias[t].x = (n0     < 52) ? s0 * (bi[r0] + bh[r0]) : 0.0f;
        bias[t].y = (n0 + 1 < 52) ? s1 * (bi[r1] + bh[r1]) : 0.0f;
    }

    // stage A once for both dirs: zero pads, cvt x -> fp16
    for (int i = tid; i < 256 * 24 / 8; i += 128)
        ((uint4*)At)[i] = make_uint4(0, 0, 0, 0);
    __syncthreads();
    const float* xsrc = x + ((size_t)b * TLEN + t0) * 13;
    for (int i = tid; i < 256 * 13; i += 128) {
        const int r = i / 13, c = i % 13;
        At[r * 24 + c] = __float2half(xsrc[i]);
    }
    __syncthreads();

    const int seq = dir * BATCH + b;
    const unsigned sA = (unsigned)__cvta_generic_to_shared(At);
    __half* ob = Ot[warp];

    for (int grp = (warp & 1); grp < 16; grp += 2) {
        const int rbase = grp * 16;
        unsigned a[4];
        const unsigned addr = sA + (unsigned)((rbase + (lane & 15)) * 48 + ((lane >> 4) & 1) * 16);
        ldmat4(a, addr);

#pragma unroll
        for (int t = 0; t < 7; t++) {
            float d0 = bias[t].x, d1 = bias[t].y, d2 = bias[t].x, d3 = bias[t].y;
            mma16816(d0, d1, d2, d3, a, bf[t]);
            const int n0 = 8 * t + tg * 2;
            if (n0 < 52) {
                *(__half2*)(ob + g * G4 + n0)       = __floats2half2_rn(d0, d1);
                *(__half2*)(ob + (g + 8) * G4 + n0) = __floats2half2_rn(d2, d3);
            }
        }
        __syncwarp();
        // 16 rows x 104 B contiguous in gmem = 104 uint4
        uint4* dst = (uint4*)(pre + ((size_t)seq * TLEN + t0 + rbase) * G4);
        const uint4* src = (const uint4*)ob;
        for (int i = lane; i < 104; i += 32) dst[i] = src[i];
        __syncwarp();
    }
}

// ---------------------------------------------------------------------------
// Pre kernel, layers 1-3 (tensor-core, BOTH dirs per block). A: 256x32 from
// padded y scratch (fwd cols 0-15, bwd cols 16-31), staged once per block.
// ---------------------------------------------------------------------------
__global__ void __launch_bounds__(128)
preR_kernel(const __half* __restrict__ y,     // [2][B][T][16] fp16, pads zero
            const float* __restrict__ w_ih,   // [2][52][26]
            const float* __restrict__ b_ih,
            const float* __restrict__ b_hh,
            __half* __restrict__ pre)
{
    __shared__ alignas(16) __half At[256 * 40];       // 20 KB
    __shared__ alignas(16) __half Ot[4][16 * G4];     // 4 x 1664 B

    const int tid  = threadIdx.x;
    const int lane = tid & 31;
    const int warp = tid >> 5;
    const int b    = blockIdx.x >> 4;
    const int t0   = (blockIdx.x & 15) * 256;
    const int dir  = warp >> 1;
    const int g    = lane >> 2;
    const int tg   = lane & 3;

    const float* W  = w_ih + dir * G4 * 26;
    const float* bi = b_ih + dir * G4;
    const float* bh = b_hh + dir * G4;

    unsigned bf[7][2][2];
    float2 bias[7];
#pragma unroll
    for (int t = 0; t < 7; t++) {
        const int nb = 8 * t + g;
        int row; float sc; gatemap(nb < 52 ? nb : 0, row, sc);
        const bool bv = (nb < 52);
#pragma unroll
        for (int s = 0; s < 2; s++) {
#pragma unroll
            for (int r = 0; r < 2; r++) {
                float w[2];
#pragma unroll
                for (int e = 0; e < 2; e++) {
                    const int k = s * 16 + tg * 2 + r * 8 + e;
                    float v = 0.0f;
                    if (bv) {
                        if (k < 13)                 v = sc * W[row * 26 + k];
                        else if (k >= 16 && k < 29) v = sc * W[row * 26 + k - 3];
                    }
                    w[e] = v;
                }
                bf[t][s][r] = packh2(w[0], w[1]);
            }
        }
        const int n0 = 8 * t + tg * 2;
        int r0, r1; float s0, s1;
        gatemap(n0 < 52 ? n0 : 0, r0, s0);
        gatemap(n0 + 1 < 52 ? n0 + 1 : 0, r1, s1);
        bias[t].x = (n0     < 52) ? s0 * (bi[r0] + bh[r0]) : 0.0f;
        bias[t].y = (n0 + 1 < 52) ? s1 * (bi[r1] + bh[r1]) : 0.0f;
    }

    // stage A once (both dirs read it)
    const char* yf = (const char*)(y + ((size_t)b * TLEN + t0) * YROW);
    const char* yb = (const char*)(y + ((size_t)(BATCH + b) * TLEN + t0) * YROW);
    const unsigned sA = (unsigned)__cvta_generic_to_shared(At);
    for (int i = tid; i < 512; i += 128) {
        const int r = i >> 1, h16 = i & 1;
        cp16(sA + (unsigned)(r * 80 + h16 * 16),      yf + i * 16);
        cp16(sA + (unsigned)(r * 80 + 32 + h16 * 16), yb + i * 16);
    }
    cp_commit();
    cp_wait0();
    __syncthreads();

    const int seq = dir * BATCH + b;
    __half* ob = Ot[warp];

    for (int grp = (warp & 1); grp < 16; grp += 2) {
        const int rbase = grp * 16;
        unsigned a0[4], a1[4];
        const unsigned addr = sA + (unsigned)((rbase + (lane & 15)) * 80 + ((lane >> 4) & 1) * 16);
        ldmat4(a0, addr);
        ldmat4(a1, addr + 32);

#pragma unroll
        for (int t = 0; t < 7; t++) {
            float d0 = bias[t].x, d1 = bias[t].y, d2 = bias[t].x, d3 = bias[t].y;
            mma16816(d0, d1, d2, d3, a0, bf[t][0]);
            mma16816(d0, d1, d2, d3, a1, bf[t][1]);
            const int n0 = 8 * t + tg * 2;
            if (n0 < 52) {
                *(__half2*)(ob + g * G4 + n0)       = __floats2half2_rn(d0, d1);
                *(__half2*)(ob + (g + 8) * G4 + n0) = __floats2half2_rn(d2, d3);
            }
        }
        __syncwarp();
        uint4* dst = (uint4*)(pre + ((size_t)seq * TLEN + t0 + rbase) * G4);
        const uint4* src = (const uint4*)ob;
        for (int i = lane; i < 104; i += 32) dst[i] = src[i];
        __syncwarp();
    }
}

// ---------------------------------------------------------------------------
// Chunked recurrence (KCH=16, CH=256, WARM=48). Compile-time stride LDY.
// ---------------------------------------------------------------------------
template<typename OutT, int LDY>
__global__ void __launch_bounds__(32)
lstm_rec_kernel(const __half* __restrict__ pre,  // [NSEQ][TLEN][52] fp16
                const float* __restrict__ w_hh,  // [2][52][13]
                OutT* __restrict__ yout,
                size_t dirOff)
{
    __shared__ alignas(16) uint2 ring[16][32];

    const int lane = threadIdx.x;
    const int b    = blockIdx.x >> KCH_SHIFT;
    const int c    = blockIdx.x & (KCH - 1);
    const int dir  = lane >> 4;
    const int k    = lane & 15;
    const int kc   = (k < 13) ? k : 12;
    const bool act = (k < 13);

    const int Wc  = (c == 0) ? 0 : WARM;
    const int TOT = Wc + CH;

    const float* W = w_hh + dir * G4 * HID;
    u64 wA[13], wB[13];
#pragma unroll
    for (int kk = 0; kk < 13; kk++) {
        wA[kk] = pk2(0.5f * W[kc * HID + kk], 0.5f * W[(13 + kc) * HID + kk]);
        wB[kk] = pk2(W[(26 + kc) * HID + kk], 0.5f * W[(39 + kc) * HID + kk]);
    }

    const int t0f = c * CH - Wc;
    const int t0b = (KCH - 1 - c) * CH + (CH - 1) + Wc;
    const int tstart = dir ? t0b : t0f;
    const long long ss   = (dir ? -1LL : 1LL) * (long long)(G4 * sizeof(__half));
    const long long ydel = (dir ? -1LL : 1LL) * LDY;

    const int seq = dir * BATCH + b;
    const char* psrc_pf = (const char*)(pre + ((size_t)seq * TLEN + tstart) * G4 + kc * 4);
    OutT* yp = yout + (size_t)b * TLEN * LDY + (size_t)dir * dirOff
                    + (size_t)tstart * LDY + k;

    const unsigned sbase = (unsigned)__cvta_generic_to_shared(&ring[0][lane]);
    const unsigned S8    = (unsigned)(32 * sizeof(uint2));

#pragma unroll
    for (int g = 0; g < 2; g++) {
#pragma unroll
        for (int j = 0; j < 4; j++) {
            cp8(sbase + (g * 4 + j) * S8, psrc_pf);
            psrc_pf += ss;
        }
        cp_commit();
    }

    float h = 0.0f, cv = 0.0f;

    for (int sblk = 0; sblk < TOT; sblk += 16) {
        const bool real = (sblk >= Wc);
#pragma unroll
        for (int qq = 0; qq < 4; qq++) {
            const int bs = sblk + qq * 4;
            if (bs + 8 < TOT) {
                const unsigned qs = (((unsigned)(bs >> 2) + 2u) & 3u) * 4u;
#pragma unroll
                for (int j = 0; j < 4; j++)
                    cp8(sbase + (qs + j) * S8, psrc_pf + (long long)j * ss);
            }
            cp_commit();
            psrc_pf += 4 * ss;
            cp_wait2();

#pragma unroll
            for (int j = 0; j < 4; j++) {
                const uint2 rv = ring[qq * 4 + j][lane];
                const float2 pif = __half22float2(*(const __half2*)&rv.x);
                const float2 pgo = __half22float2(*(const __half2*)&rv.y);

                u64 a0 = pk2(pif.x, pif.y), a1 = pk2(pgo.x, pgo.y);
                u64 c0 = 0ull, c1 = 0ull;
#pragma unroll
                for (int kk = 0; kk < 13; kk++) {
                    const float hv = __shfl_sync(0xffffffffu, h, kk, 16);
                    const u64 h2 = pk2(hv, hv);
                    if (kk & 1) { c0 = fma2(wA[kk], h2, c0); c1 = fma2(wB[kk], h2, c1); }
                    else        { a0 = fma2(wA[kk], h2, a0); a1 = fma2(wB[kk], h2, a1); }
                }
                a0 = add2(a0, c0);
                a1 = add2(a1, c1);

                const float2 g01 = upk2(a0);
                const float2 g23 = upk2(a1);
                const float tg = tanha(g23.x);
                const float si = fmaf(0.5f, tanha(g01.x), 0.5f);
                const float sf = fmaf(0.5f, tanha(g01.y), 0.5f);
                const float so = fmaf(0.5f, tanha(g23.y), 0.5f);

                cv = fmaf(sf, cv, si * tg);
                h = so * tanha(cv);

                if (act && real) *yp = (OutT)h;
                yp += ydel;
            }
        }
    }
}

// ---------------------------------------------------------------------------
// Launch
// ---------------------------------------------------------------------------
extern "C" void kernel_launch(void* const* d_in, const int* in_sizes, int n_in,
                              void* d_out, int out_size)
{
    const float* x      = (const float*)d_in[0];
    const float* w_ih0  = (const float*)d_in[1];
    const float* w_hh0  = (const float*)d_in[2];
    const float* b_ih0  = (const float*)d_in[3];
    const float* b_hh0  = (const float*)d_in[4];
    const float* w_ihr  = (const float*)d_in[5];
    const float* w_hhr  = (const float*)d_in[6];
    const float* b_ihr  = (const float*)d_in[7];
    const float* b_hhr  = (const float*)d_in[8];
    float* out = (float*)d_out;

    __half *pre, *yA, *yB;
    cudaGetSymbolAddress((void**)&pre, g_pre);
    cudaGetSymbolAddress((void**)&yA,  g_yA);
    cudaGetSymbolAddress((void**)&yB,  g_yB);

    const int PRE_BLOCKS = BATCH * 16;            // 2048 (both dirs per block)
    const int REC_BLOCKS = BATCH * KCH;           // 2048
    const size_t Y_DIROFF = (size_t)BATCH * TLEN * YROW;

    // Layer 0
    pre0_kernel<<<PRE_BLOCKS, 128>>>(x, w_ih0, b_ih0, b_hh0, pre);
    lstm_rec_kernel<__half, YROW><<<REC_BLOCKS, 32>>>(pre, w_hh0, yA, Y_DIROFF);

    // Layers 1-2 -> padded fp16 scratch; layer 3 -> final fp32 out [B][T][26]
    const __half* ins[3] = {yA, yB, yA};
    for (int l = 0; l < 3; l++) {
        preR_kernel<<<PRE_BLOCKS, 128>>>(ins[l],
                                         w_ihr + (size_t)l * 2 * G4 * 26,
                                         b_ihr + (size_t)l * 2 * G4,
                                         b_hhr + (size_t)l * 2 * G4,
                                         pre);
        if (l < 2) {
            __half* yo = (l == 0) ? yB : yA;
            lstm_rec_kernel<__half, YROW><<<REC_BLOCKS, 32>>>(pre,
                                                w_hhr + (size_t)l * 2 * G4 * HID,
                                                yo, Y_DIROFF);
        } else {
            lstm_rec_kernel<float, 26><<<REC_BLOCKS, 32>>>(pre,
                                                w_hhr + (size_t)l * 2 * G4 * HID,
                                                out, (size_t)HID);
        }
    }
}